// round 15
// baseline (speedup 1.0000x reference)
#include <cuda_runtime.h>
#include <cuda_bf16.h>
#include <math.h>

// ---------------- problem constants ----------------
#define B_      2
#define T_      2048
#define DIM_    512
#define HEADS_  8
#define DH_     64
#define NH_     8
#define NB_     32
#define BUCKET_ 64
#define NCHUNK_ 256
#define BH_     16
#define ROWS_   4096
#define SPEC_   229
#define DEPTH_  8
#define NPITCH_ 88
#define FFN_    2048

// ---------------- packed fp32x2 helpers (sm_100+) ----------------
__device__ __forceinline__ unsigned long long pack2(float lo, float hi) {
    unsigned long long r;
    asm("mov.b64 %0, {%1, %2};" : "=l"(r) : "f"(lo), "f"(hi));
    return r;
}
__device__ __forceinline__ void unpack2(unsigned long long p, float& lo, float& hi) {
    asm("mov.b64 {%0, %1}, %2;" : "=f"(lo), "=f"(hi) : "l"(p));
}
__device__ __forceinline__ void fma2(unsigned long long& c, unsigned long long a, unsigned long long b) {
    asm("fma.rn.f32x2 %0, %1, %2, %0;" : "+l"(c) : "l"(a), "l"(b));
}

// ---------------- scratch (device globals; no allocation allowed) ----------------
__device__ float g_x1[ROWS_ * DIM_];
__device__ float g_x2[ROWS_ * DIM_];
__device__ float g_xn[ROWS_ * DIM_];
__device__ float g_qk[ROWS_ * DIM_];
__device__ float g_v [ROWS_ * DIM_];
__device__ float g_attn[ROWS_ * DIM_];
__device__ float g_ffn[ROWS_ * FFN_];
__device__ float g_y [ROWS_ * DIM_];
__device__ int   g_bucket[BH_ * NH_ * T_];
__device__ int   g_st  [BH_ * NH_ * T_];
__device__ int   g_sidx[BH_ * NH_ * T_];
__device__ float g_so  [BH_ * NH_ * T_ * DH_];
__device__ float g_sl  [BH_ * NH_ * T_];

// ---------------- conv frontend + positional embedding ----------------
__global__ void conv_pe_kernel(const float* __restrict__ spec,
                               const float* __restrict__ w,
                               const float* __restrict__ cb,
                               const float* __restrict__ pe_row,
                               const float* __restrict__ pe_col,
                               float* __restrict__ x1, float* __restrict__ x2) {
    int t = blockIdx.x, b = blockIdx.y;
    __shared__ float s[3 * SPEC_];
    int tid = threadIdx.x;
    for (int i = tid; i < 3 * SPEC_; i += 256) {
        int k = i / SPEC_, ii = i % SPEC_;
        int tt = t + k - 1;
        s[i] = (tt >= 0 && tt < T_) ? spec[(b * T_ + tt) * SPEC_ + ii] : 0.f;
    }
    __syncthreads();
    int r = b * T_ + t;
    for (int o = tid; o < DIM_; o += 256) {
        float acc = cb[o];
        const float* wo_ = w + o * SPEC_ * 3;
        for (int i = 0; i < SPEC_; i++) {
            float w0 = wo_[i * 3 + 0], w1 = wo_[i * 3 + 1], w2 = wo_[i * 3 + 2];
            acc += s[i] * w0 + s[SPEC_ + i] * w1 + s[2 * SPEC_ + i] * w2;
        }
        acc = fmaxf(acc, 0.f);
        float pe = (o < 256) ? pe_row[(t >> 6) * 256 + o]
                             : pe_col[(t & 63) * 256 + (o - 256)];
        acc += pe;
        x1[r * DIM_ + o] = acc;
        x2[r * DIM_ + o] = acc;
    }
}

// ---------------- layernorm: warp per row ----------------
__global__ void __launch_bounds__(256) ln_kernel(const float* __restrict__ x,
                                                 const float* __restrict__ g,
                                                 const float* __restrict__ bt,
                                                 float* __restrict__ y) {
    int warp = threadIdx.x >> 5, lane = threadIdx.x & 31;
    int r = blockIdx.x * 8 + warp;
    const float4* xr = (const float4*)(x + (size_t)r * DIM_);
    float4 v[4];
    float sum = 0.f, sq = 0.f;
#pragma unroll
    for (int i = 0; i < 4; i++) {
        v[i] = xr[lane + 32 * i];
        sum += v[i].x + v[i].y + v[i].z + v[i].w;
        sq += v[i].x * v[i].x + v[i].y * v[i].y + v[i].z * v[i].z + v[i].w * v[i].w;
    }
#pragma unroll
    for (int o = 16; o > 0; o >>= 1) {
        sum += __shfl_xor_sync(0xffffffffu, sum, o);
        sq  += __shfl_xor_sync(0xffffffffu, sq, o);
    }
    float mean = sum * (1.f / DIM_);
    float var = fmaxf(sq * (1.f / DIM_) - mean * mean, 0.f);
    float rstd = rsqrtf(var + 1e-5f);
    float4* yr = (float4*)(y + (size_t)r * DIM_);
#pragma unroll
    for (int i = 0; i < 4; i++) {
        int c = (lane + 32 * i) * 4;
        float4 gg = *(const float4*)(g + c);
        float4 bb = *(const float4*)(bt + c);
        float4 o;
        o.x = (v[i].x - mean) * rstd * gg.x + bb.x;
        o.y = (v[i].y - mean) * rstd * gg.y + bb.y;
        o.z = (v[i].z - mean) * rstd * gg.z + bb.z;
        o.w = (v[i].w - mean) * rstd * gg.w + bb.w;
        yr[lane + 32 * i] = o;
    }
}

// ---------------- big SGEMM (R8 proven): 128x128x16, 8x8/thread, f32x2 ----------------
__global__ void __launch_bounds__(256, 2) sgemm128_kernel(
    const float* __restrict__ A, const float* __restrict__ Bm,
    const float* __restrict__ bias, float* __restrict__ C,
    const float* __restrict__ Bm2, float* __restrict__ C2,
    int N, int K, int act, int acc) {
    if (blockIdx.z == 1) { Bm = Bm2; C = C2; }
    __shared__ __align__(16) float As[2][16][132];
    __shared__ __align__(16) float Bs[2][16][132];
    int m0 = blockIdx.y * 128, n0 = blockIdx.x * 128;
    int tid = threadIdx.x;
    int a_r = tid >> 2, a_c = (tid & 3) << 2;
    int b_r = tid >> 5, b_c = (tid & 31) << 2;
    int tr = tid >> 4, tc = tid & 15;
    int r0 = tr * 4, c0 = tc * 4;
    unsigned long long accp[8][4];
#pragma unroll
    for (int i = 0; i < 8; i++)
#pragma unroll
        for (int j = 0; j < 4; j++) accp[i][j] = 0ull;

    const float* Ap0 = A + (size_t)(m0 + a_r) * K + a_c;
    const float* Ap1 = A + (size_t)(m0 + a_r + 64) * K + a_c;
    const float* Bp0 = Bm + (size_t)b_r * N + n0 + b_c;
    const float* Bp1 = Bm + (size_t)(b_r + 8) * N + n0 + b_c;

    float4 a0 = *(const float4*)(Ap0);
    float4 a1 = *(const float4*)(Ap1);
    float4 b0 = *(const float4*)(Bp0);
    float4 b1 = *(const float4*)(Bp1);
    As[0][a_c + 0][a_r] = a0.x; As[0][a_c + 1][a_r] = a0.y;
    As[0][a_c + 2][a_r] = a0.z; As[0][a_c + 3][a_r] = a0.w;
    As[0][a_c + 0][a_r + 64] = a1.x; As[0][a_c + 1][a_r + 64] = a1.y;
    As[0][a_c + 2][a_r + 64] = a1.z; As[0][a_c + 3][a_r + 64] = a1.w;
    *(float4*)&Bs[0][b_r][b_c] = b0;
    *(float4*)&Bs[0][b_r + 8][b_c] = b1;
    __syncthreads();

    int cur = 0;
    for (int k0 = 0; k0 < K; k0 += 16) {
        bool more = (k0 + 16) < K;
        if (more) {
            a0 = *(const float4*)(Ap0 + k0 + 16);
            a1 = *(const float4*)(Ap1 + k0 + 16);
            b0 = *(const float4*)(Bp0 + (size_t)(k0 + 16) * N);
            b1 = *(const float4*)(Bp1 + (size_t)(k0 + 16) * N);
        }
#pragma unroll
        for (int k = 0; k < 16; k++) {
            float4 aA = *(const float4*)&As[cur][k][r0];
            float4 aB = *(const float4*)&As[cur][k][r0 + 64];
            ulonglong2 bA = *(const ulonglong2*)&Bs[cur][k][c0];
            ulonglong2 bB = *(const ulonglong2*)&Bs[cur][k][c0 + 64];
            unsigned long long ap[8], bp[4];
            ap[0] = pack2(aA.x, aA.x); ap[1] = pack2(aA.y, aA.y);
            ap[2] = pack2(aA.z, aA.z); ap[3] = pack2(aA.w, aA.w);
            ap[4] = pack2(aB.x, aB.x); ap[5] = pack2(aB.y, aB.y);
            ap[6] = pack2(aB.z, aB.z); ap[7] = pack2(aB.w, aB.w);
            bp[0] = bA.x; bp[1] = bA.y; bp[2] = bB.x; bp[3] = bB.y;
#pragma unroll
            for (int i = 0; i < 8; i++)
#pragma unroll
                for (int j = 0; j < 4; j++) fma2(accp[i][j], ap[i], bp[j]);
        }
        if (more) {
            int nxt = cur ^ 1;
            As[nxt][a_c + 0][a_r] = a0.x; As[nxt][a_c + 1][a_r] = a0.y;
            As[nxt][a_c + 2][a_r] = a0.z; As[nxt][a_c + 3][a_r] = a0.w;
            As[nxt][a_c + 0][a_r + 64] = a1.x; As[nxt][a_c + 1][a_r + 64] = a1.y;
            As[nxt][a_c + 2][a_r + 64] = a1.z; As[nxt][a_c + 3][a_r + 64] = a1.w;
            *(float4*)&Bs[nxt][b_r][b_c] = b0;
            *(float4*)&Bs[nxt][b_r + 8][b_c] = b1;
            __syncthreads();
            cur = nxt;
        }
    }
#pragma unroll
    for (int i = 0; i < 8; i++) {
        int m = m0 + ((i < 4) ? (r0 + i) : (64 + r0 + i - 4));
#pragma unroll
        for (int j = 0; j < 4; j++) {
            float lo, hi;
            unpack2(accp[i][j], lo, hi);
            int n = n0 + ((j < 2) ? (c0 + 2 * j) : (64 + c0 + 2 * (j - 2)));
            float v0 = lo + (bias ? bias[n] : 0.f);
            float v1 = hi + (bias ? bias[n + 1] : 0.f);
            if (act == 2) {
                v0 = 0.5f * v0 * (1.f + erff(v0 * 0.70710678118654752f));
                v1 = 0.5f * v1 * (1.f + erff(v1 * 0.70710678118654752f));
            }
            float* p = C + (size_t)m * N + n;
            if (acc) { p[0] += v0; p[1] += v1; }
            else     { p[0] = v0;  p[1] = v1; }
        }
    }
}

// ---------------- small SGEMM (N=88 final projection) ----------------
__global__ void sgemm_kernel(const float* __restrict__ A, const float* __restrict__ B,
                             const float* __restrict__ bias, float* __restrict__ C,
                             int M, int N, int K, int act, int acc) {
    __shared__ float As[16][65];
    __shared__ float Bs[16][65];
    int m0 = blockIdx.y * 64, n0 = blockIdx.x * 64;
    int tid = threadIdx.x;
    int tc = tid & 15, tr = tid >> 4;
    int a_r = tid >> 2, a_c0 = (tid & 3) * 4;
    int b_r = tid >> 4, b_c0 = (tid & 15) * 4;
    float accv[4][4] = {};
    for (int k0 = 0; k0 < K; k0 += 16) {
        const float* Ap = A + (m0 + a_r) * K + k0 + a_c0;
#pragma unroll
        for (int j = 0; j < 4; j++) As[a_c0 + j][a_r] = Ap[j];
#pragma unroll
        for (int j = 0; j < 4; j++) {
            int n = n0 + b_c0 + j;
            Bs[b_r][b_c0 + j] = (n < N) ? B[(k0 + b_r) * N + n] : 0.f;
        }
        __syncthreads();
#pragma unroll
        for (int k = 0; k < 16; k++) {
            float av[4], bv[4];
#pragma unroll
            for (int i = 0; i < 4; i++) av[i] = As[k][tr * 4 + i];
#pragma unroll
            for (int j = 0; j < 4; j++) bv[j] = Bs[k][tc * 4 + j];
#pragma unroll
            for (int i = 0; i < 4; i++)
#pragma unroll
                for (int j = 0; j < 4; j++) accv[i][j] += av[i] * bv[j];
        }
        __syncthreads();
    }
#pragma unroll
    for (int i = 0; i < 4; i++) {
        int m = m0 + tr * 4 + i;
#pragma unroll
        for (int j = 0; j < 4; j++) {
            int n = n0 + tc * 4 + j;
            if (n < N) {
                float val = accv[i][j] + (bias ? bias[n] : 0.f);
                if (act == 2) val = 0.5f * val * (1.f + erff(val * 0.70710678118654752f));
                C[m * N + n] = acc ? (C[m * N + n] + val) : val;
            }
        }
    }
}

// ---------------- LSH bucketing as GEMM tile + argmax ----------------
#define BK_QT 68
#define BK_RS 132
#define BKT_SMEM ((64 * BK_QT + 64 * BK_RS + 64 * BK_RS) * 4)
__global__ void __launch_bounds__(256) bucket_kernel(const float* __restrict__ qk,
                                                     const float* __restrict__ rotL,
                                                     int* __restrict__ bucket) {
    extern __shared__ float bsm[];
    float* qsT = bsm;
    float* rs  = qsT + 64 * BK_QT;
    float* dt  = rs + 64 * BK_RS;
    int tid = threadIdx.x;
    int bh = blockIdx.y;
    int b = bh >> 3, hd = bh & 7;
    int t0 = blockIdx.x * 64;
#pragma unroll
    for (int it = 0; it < 4; it++) {
        int lin = tid + it * 256;
        int tok = lin >> 4, c4 = (lin & 15) << 2;
        float4 qv = *(const float4*)(qk + (size_t)(b * T_ + t0 + tok) * DIM_ + hd * DH_ + c4);
        qsT[(c4 + 0) * BK_QT + tok] = qv.x;
        qsT[(c4 + 1) * BK_QT + tok] = qv.y;
        qsT[(c4 + 2) * BK_QT + tok] = qv.z;
        qsT[(c4 + 3) * BK_QT + tok] = qv.w;
    }
#pragma unroll
    for (int it = 0; it < 8; it++) {
        int lin = tid + it * 256;
        int f = lin >> 5, c4 = (lin & 31) << 2;
        *(float4*)(rs + f * BK_RS + c4) = *(const float4*)(rotL + f * 128 + c4);
    }
    __syncthreads();
    {
        int tq = tid >> 4, tk = tid & 15;
        int tok0 = tq * 4, o0 = tk * 8;
        unsigned long long acc[4][4];
#pragma unroll
        for (int i = 0; i < 4; i++)
#pragma unroll
            for (int j = 0; j < 4; j++) acc[i][j] = 0ull;
#pragma unroll 4
        for (int f = 0; f < 64; f++) {
            float4 qv = *(const float4*)(qsT + f * BK_QT + tok0);
            ulonglong2 rA = *(const ulonglong2*)(rs + f * BK_RS + o0);
            ulonglong2 rB = *(const ulonglong2*)(rs + f * BK_RS + o0 + 4);
            unsigned long long qp[4], rp[4];
            qp[0] = pack2(qv.x, qv.x); qp[1] = pack2(qv.y, qv.y);
            qp[2] = pack2(qv.z, qv.z); qp[3] = pack2(qv.w, qv.w);
            rp[0] = rA.x; rp[1] = rA.y; rp[2] = rB.x; rp[3] = rB.y;
#pragma unroll
            for (int i = 0; i < 4; i++)
#pragma unroll
                for (int j = 0; j < 4; j++) fma2(acc[i][j], qp[i], rp[j]);
        }
#pragma unroll
        for (int i = 0; i < 4; i++)
#pragma unroll
            for (int j = 0; j < 4; j++) {
                float lo, hi;
                unpack2(acc[i][j], lo, hi);
                dt[(tok0 + i) * BK_RS + o0 + 2 * j] = lo;
                dt[(tok0 + i) * BK_RS + o0 + 2 * j + 1] = hi;
            }
    }
    __syncthreads();
#pragma unroll
    for (int rep = 0; rep < 2; rep++) {
        int pair = tid + rep * 256;
        int tok = pair >> 3, h = pair & 7;
        const float* row = dt + tok * BK_RS + h * 16;
        float a[16];
#pragma unroll
        for (int j = 0; j < 16; j++) a[j] = row[j];
        float best = a[0]; int bj = 0;
#pragma unroll
        for (int j = 1; j < 16; j++) if (a[j] > best) { best = a[j]; bj = j; }
#pragma unroll
        for (int j = 0; j < 16; j++) { float nv = -a[j]; if (nv > best) { best = nv; bj = 16 + j; } }
        bucket[(bh * NH_ + h) * T_ + t0 + tok] = bj;
    }
}

// ---------------- exact stable sort: warp-per-bucket ballot scan ----------------
__global__ void __launch_bounds__(1024) sort_kernel(const int* __restrict__ bucket,
                                                    int* __restrict__ st, int* __restrict__ sidx) {
    int h = blockIdx.x, bh = blockIdx.y;
    const int* bk = bucket + (bh * NH_ + h) * T_;
    int wid = threadIdx.x >> 5, lane = threadIdx.x & 31;
    __shared__ int pref[32];
    int cnt = 0;
    for (int i = 0; i < T_ / 32; i++) {
        int bb = bk[i * 32 + lane];
        unsigned mask = __ballot_sync(0xffffffffu, bb == wid);
        cnt += __popc(mask);
    }
    if (lane == 0) pref[wid] = cnt;
    __syncthreads();
    if (wid == 0) {
        int vv = pref[lane];
        int ex = vv;
        for (int o = 1; o < 32; o <<= 1) {
            int n = __shfl_up_sync(0xffffffffu, ex, o);
            if (lane >= o) ex += n;
        }
        pref[lane] = ex - vv;
    }
    __syncthreads();
    int base = bh * (NH_ * T_);
    int off = h * T_ + pref[wid];
    unsigned lt = (1u << lane) - 1u;
    for (int i = 0; i < T_ / 32; i++) {
        int p = i * 32 + lane;
        int bb = bk[p];
        unsigned mask = __ballot_sync(0xffffffffu, bb == wid);
        if (bb == wid) {
            int r = __popc(mask & lt);
            st[base + off + r] = p;
            sidx[base + h * T_ + p] = off + r;
        }
        off += __popc(mask);
    }
}

// ---------------- identity init for st (profiling probe support) ----------------
__global__ void init_st_kernel(int* __restrict__ st) {
    int i = blockIdx.x * 256 + threadIdx.x;
    if (i < BH_ * NH_ * T_) st[i] = i & (T_ - 1);
}

// ---------------- chunked attention ----------------
#define KST_STR 132
#define VS_STR  68
#define DOT_STR 130
#define ATT_SMEM ((64 * KST_STR + 128 * VS_STR + 64 * DOT_STR + 128 + 64) * 4 + 128 * 4)

__global__ void __launch_bounds__(256) attn2_kernel(const float* __restrict__ qk,
                                                    const float* __restrict__ v,
                                                    const int* __restrict__ st,
                                                    float* __restrict__ so,
                                                    float* __restrict__ sl) {
    int c = blockIdx.x;
    int bh = blockIdx.y;
    extern __shared__ float sm[];
    float* ksT  = sm;
    float* vs   = ksT + 64 * KST_STR;
    float* dots = vs + 128 * VS_STR;
    float* nrm  = dots + 64 * DOT_STR;
    float* rcp  = nrm + 128;
    int*   pk   = (int*)(rcp + 64);
    int tid = threadIdx.x;
    int b = bh >> 3, hd = bh & 7;
    int cp = (c + NCHUNK_ - 1) & (NCHUNK_ - 1);
    {
        int kk = tid >> 1, h = tid & 1;
        int cc = (kk < 64) ? c : cp;
        int p = st[bh * (NH_ * T_) + cc * 64 + (kk & 63)];
        if (!h) pk[kk] = p;
        const float* qr = qk + (size_t)(b * T_ + p) * DIM_ + hd * DH_ + h * 32;
        const float* vr = v  + (size_t)(b * T_ + p) * DIM_ + hd * DH_ + h * 32;
        float4 qv[8];
        float ss = 0.f;
#pragma unroll
        for (int i = 0; i < 8; i++) {
            qv[i] = *(const float4*)(qr + i * 4);
            ss += qv[i].x * qv[i].x + qv[i].y * qv[i].y + qv[i].z * qv[i].z + qv[i].w * qv[i].w;
        }
        float tot = ss + __shfl_xor_sync(0xffffffffu, ss, 1);
        float cl = fmaxf(sqrtf(tot), 1e-12f);
        if (!h) nrm[kk] = cl;
        float rn = 1.f / cl;
#pragma unroll
        for (int i = 0; i < 8; i++) {
            int f = h * 32 + i * 4;
            ksT[(f + 0) * KST_STR + kk] = qv[i].x * rn;
            ksT[(f + 1) * KST_STR + kk] = qv[i].y * rn;
            ksT[(f + 2) * KST_STR + kk] = qv[i].z * rn;
            ksT[(f + 3) * KST_STR + kk] = qv[i].w * rn;
            *(float4*)(vs + kk * VS_STR + f) = *(const float4*)(vr + i * 4);
        }
    }
    __syncthreads();
    {
        int tq = tid >> 4, tk = tid & 15;
        int q0 = tq * 4, k0 = tk * 8;
        unsigned long long acc[4][4];
#pragma unroll
        for (int i = 0; i < 4; i++)
#pragma unroll
            for (int j = 0; j < 4; j++) acc[i][j] = 0ull;
#pragma unroll 4
        for (int f = 0; f < 64; f++) {
            const float* row = ksT + f * KST_STR;
            float4 qv = *(const float4*)(row + q0);
            ulonglong2 kA = *(const ulonglong2*)(row + k0);
            ulonglong2 kB = *(const ulonglong2*)(row + k0 + 4);
            unsigned long long qp[4], kp[4];
            qp[0] = pack2(qv.x, qv.x); qp[1] = pack2(qv.y, qv.y);
            qp[2] = pack2(qv.z, qv.z); qp[3] = pack2(qv.w, qv.w);
            kp[0] = kA.x; kp[1] = kA.y; kp[2] = kB.x; kp[3] = kB.y;
#pragma unroll
            for (int i = 0; i < 4; i++)
#pragma unroll
                for (int j = 0; j < 4; j++) fma2(acc[i][j], qp[i], kp[j]);
        }
#pragma unroll
        for (int i = 0; i < 4; i++)
#pragma unroll
            for (int j = 0; j < 4; j++) {
                float lo, hi;
                unpack2(acc[i][j], lo, hi);
                dots[(q0 + i) * DOT_STR + k0 + 2 * j] = lo;
                dots[(q0 + i) * DOT_STR + k0 + 2 * j + 1] = hi;
            }
    }
    __syncthreads();
    {
        int q = tid >> 2, sub = tid & 3;
        float sc = nrm[q] * 0.125f;
        int pq = pk[q];
        int k0 = sub * 32;
        float m = -INFINITY;
#pragma unroll 8
        for (int i = 0; i < 32; i++) {
            float d = dots[q * DOT_STR + k0 + i] * sc;
            if (pk[k0 + i] == pq) d = -5e4f;
            m = fmaxf(m, d);
        }
        m = fmaxf(m, __shfl_xor_sync(0xffffffffu, m, 1));
        m = fmaxf(m, __shfl_xor_sync(0xffffffffu, m, 2));
        float s = 0.f;
#pragma unroll 8
        for (int i = 0; i < 32; i++) {
            float d = dots[q * DOT_STR + k0 + i] * sc;
            if (pk[k0 + i] == pq) d = -5e4f;
            float e = expf(d - m);
            dots[q * DOT_STR + k0 + i] = e;
            s += e;
        }
        s += __shfl_xor_sync(0xffffffffu, s, 1);
        s += __shfl_xor_sync(0xffffffffu, s, 2);
        if (sub == 0) {
            rcp[q] = 1.f / s;
            sl[bh * (NH_ * T_) + c * 64 + q] = m + logf(s);
        }
    }
    __syncthreads();
    {
        int tq = tid >> 4, tf = tid & 15;
        int q0 = tq * 4, f0 = tf * 4;
        unsigned long long acc[4][2];
#pragma unroll
        for (int i = 0; i < 4; i++) { acc[i][0] = 0ull; acc[i][1] = 0ull; }
#pragma unroll 2
        for (int kk = 0; kk < 128; kk++) {
            ulonglong2 vv = *(const ulonglong2*)(vs + kk * VS_STR + f0);
#pragma unroll
            for (int i = 0; i < 4; i++) {
                float p = dots[(q0 + i) * DOT_STR + kk];
                unsigned long long pp = pack2(p, p);
                fma2(acc[i][0], pp, vv.x);
                fma2(acc[i][1], pp, vv.y);
            }
        }
#pragma unroll
        for (int i = 0; i < 4; i++) {
            float r = rcp[q0 + i];
            size_t base = ((size_t)bh * (NH_ * T_) + c * 64 + q0 + i) * DH_ + f0;
#pragma unroll
            for (int j = 0; j < 2; j++) {
                float lo, hi;
                unpack2(acc[i][j], lo, hi);
                float2 o2 = make_float2(lo * r, hi * r);
                *(float2*)(so + base + 2 * j) = o2;
            }
        }
    }
}

// ---------------- combine hash rounds ----------------
__global__ void __launch_bounds__(256) combine_kernel(const float* __restrict__ so,
                                                      const float* __restrict__ sl,
                                                      const int* __restrict__ sidx,
                                                      float* __restrict__ attn) {
    int t = blockIdx.x * 4 + (threadIdx.x >> 6);
    int bh = blockIdx.y;
    int f = threadIdx.x & 63;
    int b = bh >> 3, hd = bh & 7;
    int sbase = bh * (NH_ * T_);
    int sarr[NH_]; float lg[NH_];
    float m = -INFINITY;
#pragma unroll
    for (int h = 0; h < NH_; h++) {
        int s = sidx[sbase + h * T_ + t];
        sarr[h] = s;
        lg[h] = sl[sbase + s];
        m = fmaxf(m, lg[h]);
    }
    float den = 0.f;
#pragma unroll
    for (int h = 0; h < NH_; h++) den += expf(lg[h] - m);
    float out = 0.f;
#pragma unroll
    for (int h = 0; h < NH_; h++)
        out += (expf(lg[h] - m) / den) * so[((size_t)sbase + sarr[h]) * DH_ + f];
    attn[(b * T_ + t) * DIM_ + hd * DH_ + f] = out;
}

// ---------------- y = 0.5*(x1+x2) ----------------
__global__ void avg_kernel(const float* __restrict__ x1, const float* __restrict__ x2,
                           float* __restrict__ y, int n) {
    int i = blockIdx.x * blockDim.x + threadIdx.x;
    if (i < n) y[i] = 0.5f * (x1[i] + x2[i]);
}

// ---------------- host orchestration ----------------
static float* sym_f(const void* s) { void* p = nullptr; cudaGetSymbolAddress(&p, s); return (float*)p; }
static int*   sym_i(const void* s) { void* p = nullptr; cudaGetSymbolAddress(&p, s); return (int*)p; }

extern "C" void kernel_launch(void* const* d_in, const int* in_sizes, int n_in,
                              void* d_out, int out_size) {
    const float* spec   = (const float*)d_in[0];
    const float* conv_w = (const float*)d_in[1];
    const float* conv_b = (const float*)d_in[2];
    const float* pe_row = (const float*)d_in[3];
    const float* pe_col = (const float*)d_in[4];
    const float* lnA_g  = (const float*)d_in[5];
    const float* lnA_b  = (const float*)d_in[6];
    const float* wqk    = (const float*)d_in[7];
    const float* wv     = (const float*)d_in[8];
    const float* wo     = (const float*)d_in[9];
    const float* bo     = (const float*)d_in[10];
    const float* lnF_g  = (const float*)d_in[11];
    const float* lnF_b  = (const float*)d_in[12];
    const float* w1     = (const float*)d_in[13];
    const float* b1     = (const float*)d_in[14];
    const float* w2     = (const float*)d_in[15];
    const float* b2     = (const float*)d_in[16];
    const float* lin_w  = (const float*)d_in[17];
    const float* lin_b  = (const float*)d_in[18];
    const float* rot    = (const float*)d_in[19];
    float* out = (float*)d_out;

    float* x1   = sym_f(g_x1);
    float* x2   = sym_f(g_x2);
    float* xn   = sym_f(g_xn);
    float* qkb  = sym_f(g_qk);
    float* vb   = sym_f(g_v);
    float* attn = sym_f(g_attn);
    float* ffn  = sym_f(g_ffn);
    float* yb   = sym_f(g_y);
    float* so   = sym_f(g_so);
    float* sl   = sym_f(g_sl);
    int* bucket = sym_i(g_bucket);
    int* st     = sym_i(g_st);
    int* sidx   = sym_i(g_sidx);

    cudaFuncSetAttribute(attn2_kernel, cudaFuncAttributeMaxDynamicSharedMemorySize, ATT_SMEM);
    cudaFuncSetAttribute(bucket_kernel, cudaFuncAttributeMaxDynamicSharedMemorySize, BKT_SMEM);

    // frontend
    conv_pe_kernel<<<dim3(T_, B_), 256>>>(spec, conv_w, conv_b, pe_row, pe_col, x1, x2);

    dim3 gQKV(DIM_ / 128, ROWS_ / 128, 2);
    dim3 g512(DIM_ / 128, ROWS_ / 128, 1);
    dim3 gffn(FFN_ / 128, ROWS_ / 128, 1);
    dim3 gout((NPITCH_ + 63) / 64, ROWS_ / 64);

    for (int l = 0; l < DEPTH_; l++) {
        const float* Wqk = wqk + (size_t)l * DIM_ * DIM_;
        const float* Wv  = wv  + (size_t)l * DIM_ * DIM_;
        const float* Wo  = wo  + (size_t)l * DIM_ * DIM_;
        const float* Bo  = bo  + (size_t)l * DIM_;
        const float* W1  = w1  + (size_t)l * DIM_ * FFN_;
        const float* B1  = b1  + (size_t)l * FFN_;
        const float* W2  = w2  + (size_t)l * DIM_ * FFN_;
        const float* B2  = b2  + (size_t)l * DIM_;
        const float* rotL = rot + (size_t)l * DH_ * NH_ * 16;

        // attention branch
        ln_kernel<<<ROWS_ / 8, 256>>>(x2, lnA_g + l * DIM_, lnA_b + l * DIM_, xn);
        if (l == 0) {
            // idx 2: identity st init; idx 3 (ncu-captured): attn2 probe.
            // Probe outputs (so/sl) are fully overwritten by the real attn2 below.
            init_st_kernel<<<(BH_ * NH_ * T_ + 255) / 256, 256>>>(st);
            attn2_kernel<<<dim3(NCHUNK_, BH_), 256, ATT_SMEM>>>(x1, x2, st, so, sl);
        }
        sgemm128_kernel<<<gQKV, 256>>>(xn, Wqk, nullptr, qkb, Wv, vb, DIM_, DIM_, 0, 0);
        bucket_kernel<<<dim3(T_ / 64, BH_), 256, BKT_SMEM>>>(qkb, rotL, bucket);
        sort_kernel<<<dim3(NH_, BH_), 1024>>>(bucket, st, sidx);
        attn2_kernel<<<dim3(NCHUNK_, BH_), 256, ATT_SMEM>>>(qkb, vb, st, so, sl);
        combine_kernel<<<dim3(T_ / 4, BH_), 256>>>(so, sl, sidx, attn);
        sgemm128_kernel<<<g512, 256>>>(attn, Wo, Bo, x1, nullptr, nullptr, DIM_, DIM_, 0, 1);

        // ffn branch
        ln_kernel<<<ROWS_ / 8, 256>>>(x1, lnF_g + l * DIM_, lnF_b + l * DIM_, xn);
        sgemm128_kernel<<<gffn, 256>>>(xn, W1, B1, ffn, nullptr, nullptr, FFN_, DIM_, 2, 0);
        sgemm128_kernel<<<g512, 256>>>(ffn, W2, B2, x2, nullptr, nullptr, DIM_, FFN_, 0, 1);
    }

    avg_kernel<<<(ROWS_ * DIM_ + 255) / 256, 256>>>(x1, x2, yb, ROWS_ * DIM_);
    sgemm_kernel<<<gout, 256>>>(yb, lin_w, lin_b, out, ROWS_, NPITCH_, DIM_, 0, 0);
}

// round 16
// speedup vs baseline: 1.1199x; 1.1199x over previous
#include <cuda_runtime.h>
#include <cuda_bf16.h>
#include <math.h>

// ---------------- problem constants ----------------
#define B_      2
#define T_      2048
#define DIM_    512
#define HEADS_  8
#define DH_     64
#define NH_     8
#define NB_     32
#define BUCKET_ 64
#define NCHUNK_ 256
#define BH_     16
#define ROWS_   4096
#define SPEC_   229
#define DEPTH_  8
#define NPITCH_ 88
#define FFN_    2048

// ---------------- packed fp32x2 helpers (sm_100+) ----------------
__device__ __forceinline__ unsigned long long pack2(float lo, float hi) {
    unsigned long long r;
    asm("mov.b64 %0, {%1, %2};" : "=l"(r) : "f"(lo), "f"(hi));
    return r;
}
__device__ __forceinline__ void unpack2(unsigned long long p, float& lo, float& hi) {
    asm("mov.b64 {%0, %1}, %2;" : "=f"(lo), "=f"(hi) : "l"(p));
}
__device__ __forceinline__ void fma2(unsigned long long& c, unsigned long long a, unsigned long long b) {
    asm("fma.rn.f32x2 %0, %1, %2, %0;" : "+l"(c) : "l"(a), "l"(b));
}

// ---------------- scratch (device globals; no allocation allowed) ----------------
__device__ float g_x1[ROWS_ * DIM_];
__device__ float g_x2[ROWS_ * DIM_];
__device__ float g_xn[ROWS_ * DIM_];
__device__ float g_qk[ROWS_ * DIM_];
__device__ float g_v [ROWS_ * DIM_];
__device__ float g_attn[ROWS_ * DIM_];
__device__ float g_ffn[ROWS_ * FFN_];
__device__ float g_y [ROWS_ * DIM_];
__device__ int   g_bucket[BH_ * NH_ * T_];
__device__ int   g_st  [BH_ * NH_ * T_];
__device__ int   g_sidx[BH_ * NH_ * T_];
__device__ float g_so  [BH_ * NH_ * T_ * DH_];
__device__ float g_sl  [BH_ * NH_ * T_];

// ---------------- conv frontend + positional embedding ----------------
__global__ void conv_pe_kernel(const float* __restrict__ spec,
                               const float* __restrict__ w,
                               const float* __restrict__ cb,
                               const float* __restrict__ pe_row,
                               const float* __restrict__ pe_col,
                               float* __restrict__ x1, float* __restrict__ x2) {
    int t = blockIdx.x, b = blockIdx.y;
    __shared__ float s[3 * SPEC_];
    int tid = threadIdx.x;
    for (int i = tid; i < 3 * SPEC_; i += 256) {
        int k = i / SPEC_, ii = i % SPEC_;
        int tt = t + k - 1;
        s[i] = (tt >= 0 && tt < T_) ? spec[(b * T_ + tt) * SPEC_ + ii] : 0.f;
    }
    __syncthreads();
    int r = b * T_ + t;
    for (int o = tid; o < DIM_; o += 256) {
        float acc = cb[o];
        const float* wo_ = w + o * SPEC_ * 3;
        for (int i = 0; i < SPEC_; i++) {
            float w0 = wo_[i * 3 + 0], w1 = wo_[i * 3 + 1], w2 = wo_[i * 3 + 2];
            acc += s[i] * w0 + s[SPEC_ + i] * w1 + s[2 * SPEC_ + i] * w2;
        }
        acc = fmaxf(acc, 0.f);
        float pe = (o < 256) ? pe_row[(t >> 6) * 256 + o]
                             : pe_col[(t & 63) * 256 + (o - 256)];
        acc += pe;
        x1[r * DIM_ + o] = acc;
        x2[r * DIM_ + o] = acc;
    }
}

// ---------------- layernorm: warp per row ----------------
__global__ void __launch_bounds__(256) ln_kernel(const float* __restrict__ x,
                                                 const float* __restrict__ g,
                                                 const float* __restrict__ bt,
                                                 float* __restrict__ y) {
    int warp = threadIdx.x >> 5, lane = threadIdx.x & 31;
    int r = blockIdx.x * 8 + warp;
    const float4* xr = (const float4*)(x + (size_t)r * DIM_);
    float4 v[4];
    float sum = 0.f, sq = 0.f;
#pragma unroll
    for (int i = 0; i < 4; i++) {
        v[i] = xr[lane + 32 * i];
        sum += v[i].x + v[i].y + v[i].z + v[i].w;
        sq += v[i].x * v[i].x + v[i].y * v[i].y + v[i].z * v[i].z + v[i].w * v[i].w;
    }
#pragma unroll
    for (int o = 16; o > 0; o >>= 1) {
        sum += __shfl_xor_sync(0xffffffffu, sum, o);
        sq  += __shfl_xor_sync(0xffffffffu, sq, o);
    }
    float mean = sum * (1.f / DIM_);
    float var = fmaxf(sq * (1.f / DIM_) - mean * mean, 0.f);
    float rstd = rsqrtf(var + 1e-5f);
    float4* yr = (float4*)(y + (size_t)r * DIM_);
#pragma unroll
    for (int i = 0; i < 4; i++) {
        int c = (lane + 32 * i) * 4;
        float4 gg = *(const float4*)(g + c);
        float4 bb = *(const float4*)(bt + c);
        float4 o;
        o.x = (v[i].x - mean) * rstd * gg.x + bb.x;
        o.y = (v[i].y - mean) * rstd * gg.y + bb.y;
        o.z = (v[i].z - mean) * rstd * gg.z + bb.z;
        o.w = (v[i].w - mean) * rstd * gg.w + bb.w;
        yr[lane + 32 * i] = o;
    }
}

// ---------------- big SGEMM (R8 proven): 128x128x16, 8x8/thread, f32x2 ----------------
__global__ void __launch_bounds__(256, 2) sgemm128_kernel(
    const float* __restrict__ A, const float* __restrict__ Bm,
    const float* __restrict__ bias, float* __restrict__ C,
    const float* __restrict__ Bm2, float* __restrict__ C2,
    int N, int K, int act, int acc) {
    if (blockIdx.z == 1) { Bm = Bm2; C = C2; }
    __shared__ __align__(16) float As[2][16][132];
    __shared__ __align__(16) float Bs[2][16][132];
    int m0 = blockIdx.y * 128, n0 = blockIdx.x * 128;
    int tid = threadIdx.x;
    int a_r = tid >> 2, a_c = (tid & 3) << 2;
    int b_r = tid >> 5, b_c = (tid & 31) << 2;
    int tr = tid >> 4, tc = tid & 15;
    int r0 = tr * 4, c0 = tc * 4;
    unsigned long long accp[8][4];
#pragma unroll
    for (int i = 0; i < 8; i++)
#pragma unroll
        for (int j = 0; j < 4; j++) accp[i][j] = 0ull;

    const float* Ap0 = A + (size_t)(m0 + a_r) * K + a_c;
    const float* Ap1 = A + (size_t)(m0 + a_r + 64) * K + a_c;
    const float* Bp0 = Bm + (size_t)b_r * N + n0 + b_c;
    const float* Bp1 = Bm + (size_t)(b_r + 8) * N + n0 + b_c;

    float4 a0 = *(const float4*)(Ap0);
    float4 a1 = *(const float4*)(Ap1);
    float4 b0 = *(const float4*)(Bp0);
    float4 b1 = *(const float4*)(Bp1);
    As[0][a_c + 0][a_r] = a0.x; As[0][a_c + 1][a_r] = a0.y;
    As[0][a_c + 2][a_r] = a0.z; As[0][a_c + 3][a_r] = a0.w;
    As[0][a_c + 0][a_r + 64] = a1.x; As[0][a_c + 1][a_r + 64] = a1.y;
    As[0][a_c + 2][a_r + 64] = a1.z; As[0][a_c + 3][a_r + 64] = a1.w;
    *(float4*)&Bs[0][b_r][b_c] = b0;
    *(float4*)&Bs[0][b_r + 8][b_c] = b1;
    __syncthreads();

    int cur = 0;
    for (int k0 = 0; k0 < K; k0 += 16) {
        bool more = (k0 + 16) < K;
        if (more) {
            a0 = *(const float4*)(Ap0 + k0 + 16);
            a1 = *(const float4*)(Ap1 + k0 + 16);
            b0 = *(const float4*)(Bp0 + (size_t)(k0 + 16) * N);
            b1 = *(const float4*)(Bp1 + (size_t)(k0 + 16) * N);
        }
#pragma unroll
        for (int k = 0; k < 16; k++) {
            float4 aA = *(const float4*)&As[cur][k][r0];
            float4 aB = *(const float4*)&As[cur][k][r0 + 64];
            ulonglong2 bA = *(const ulonglong2*)&Bs[cur][k][c0];
            ulonglong2 bB = *(const ulonglong2*)&Bs[cur][k][c0 + 64];
            unsigned long long ap[8], bp[4];
            ap[0] = pack2(aA.x, aA.x); ap[1] = pack2(aA.y, aA.y);
            ap[2] = pack2(aA.z, aA.z); ap[3] = pack2(aA.w, aA.w);
            ap[4] = pack2(aB.x, aB.x); ap[5] = pack2(aB.y, aB.y);
            ap[6] = pack2(aB.z, aB.z); ap[7] = pack2(aB.w, aB.w);
            bp[0] = bA.x; bp[1] = bA.y; bp[2] = bB.x; bp[3] = bB.y;
#pragma unroll
            for (int i = 0; i < 8; i++)
#pragma unroll
                for (int j = 0; j < 4; j++) fma2(accp[i][j], ap[i], bp[j]);
        }
        if (more) {
            int nxt = cur ^ 1;
            As[nxt][a_c + 0][a_r] = a0.x; As[nxt][a_c + 1][a_r] = a0.y;
            As[nxt][a_c + 2][a_r] = a0.z; As[nxt][a_c + 3][a_r] = a0.w;
            As[nxt][a_c + 0][a_r + 64] = a1.x; As[nxt][a_c + 1][a_r + 64] = a1.y;
            As[nxt][a_c + 2][a_r + 64] = a1.z; As[nxt][a_c + 3][a_r + 64] = a1.w;
            *(float4*)&Bs[nxt][b_r][b_c] = b0;
            *(float4*)&Bs[nxt][b_r + 8][b_c] = b1;
            __syncthreads();
            cur = nxt;
        }
    }
#pragma unroll
    for (int i = 0; i < 8; i++) {
        int m = m0 + ((i < 4) ? (r0 + i) : (64 + r0 + i - 4));
#pragma unroll
        for (int j = 0; j < 4; j++) {
            float lo, hi;
            unpack2(accp[i][j], lo, hi);
            int n = n0 + ((j < 2) ? (c0 + 2 * j) : (64 + c0 + 2 * (j - 2)));
            float v0 = lo + (bias ? bias[n] : 0.f);
            float v1 = hi + (bias ? bias[n + 1] : 0.f);
            if (act == 2) {
                v0 = 0.5f * v0 * (1.f + erff(v0 * 0.70710678118654752f));
                v1 = 0.5f * v1 * (1.f + erff(v1 * 0.70710678118654752f));
            }
            float* p = C + (size_t)m * N + n;
            if (acc) { p[0] += v0; p[1] += v1; }
            else     { p[0] = v0;  p[1] = v1; }
        }
    }
}

// ---------------- small SGEMM (N=88 final projection) ----------------
__global__ void sgemm_kernel(const float* __restrict__ A, const float* __restrict__ B,
                             const float* __restrict__ bias, float* __restrict__ C,
                             int M, int N, int K, int act, int acc) {
    __shared__ float As[16][65];
    __shared__ float Bs[16][65];
    int m0 = blockIdx.y * 64, n0 = blockIdx.x * 64;
    int tid = threadIdx.x;
    int tc = tid & 15, tr = tid >> 4;
    int a_r = tid >> 2, a_c0 = (tid & 3) * 4;
    int b_r = tid >> 4, b_c0 = (tid & 15) * 4;
    float accv[4][4] = {};
    for (int k0 = 0; k0 < K; k0 += 16) {
        const float* Ap = A + (m0 + a_r) * K + k0 + a_c0;
#pragma unroll
        for (int j = 0; j < 4; j++) As[a_c0 + j][a_r] = Ap[j];
#pragma unroll
        for (int j = 0; j < 4; j++) {
            int n = n0 + b_c0 + j;
            Bs[b_r][b_c0 + j] = (n < N) ? B[(k0 + b_r) * N + n] : 0.f;
        }
        __syncthreads();
#pragma unroll
        for (int k = 0; k < 16; k++) {
            float av[4], bv[4];
#pragma unroll
            for (int i = 0; i < 4; i++) av[i] = As[k][tr * 4 + i];
#pragma unroll
            for (int j = 0; j < 4; j++) bv[j] = Bs[k][tc * 4 + j];
#pragma unroll
            for (int i = 0; i < 4; i++)
#pragma unroll
                for (int j = 0; j < 4; j++) accv[i][j] += av[i] * bv[j];
        }
        __syncthreads();
    }
#pragma unroll
    for (int i = 0; i < 4; i++) {
        int m = m0 + tr * 4 + i;
#pragma unroll
        for (int j = 0; j < 4; j++) {
            int n = n0 + tc * 4 + j;
            if (n < N) {
                float val = accv[i][j] + (bias ? bias[n] : 0.f);
                if (act == 2) val = 0.5f * val * (1.f + erff(val * 0.70710678118654752f));
                C[m * N + n] = acc ? (C[m * N + n] + val) : val;
            }
        }
    }
}

// ---------------- LSH bucketing as GEMM tile + argmax ----------------
#define BK_QT 68
#define BK_RS 132
#define BKT_SMEM ((64 * BK_QT + 64 * BK_RS + 64 * BK_RS) * 4)
__global__ void __launch_bounds__(256) bucket_kernel(const float* __restrict__ qk,
                                                     const float* __restrict__ rotL,
                                                     int* __restrict__ bucket) {
    extern __shared__ float bsm[];
    float* qsT = bsm;
    float* rs  = qsT + 64 * BK_QT;
    float* dt  = rs + 64 * BK_RS;
    int tid = threadIdx.x;
    int bh = blockIdx.y;
    int b = bh >> 3, hd = bh & 7;
    int t0 = blockIdx.x * 64;
#pragma unroll
    for (int it = 0; it < 4; it++) {
        int lin = tid + it * 256;
        int tok = lin >> 4, c4 = (lin & 15) << 2;
        float4 qv = *(const float4*)(qk + (size_t)(b * T_ + t0 + tok) * DIM_ + hd * DH_ + c4);
        qsT[(c4 + 0) * BK_QT + tok] = qv.x;
        qsT[(c4 + 1) * BK_QT + tok] = qv.y;
        qsT[(c4 + 2) * BK_QT + tok] = qv.z;
        qsT[(c4 + 3) * BK_QT + tok] = qv.w;
    }
#pragma unroll
    for (int it = 0; it < 8; it++) {
        int lin = tid + it * 256;
        int f = lin >> 5, c4 = (lin & 31) << 2;
        *(float4*)(rs + f * BK_RS + c4) = *(const float4*)(rotL + f * 128 + c4);
    }
    __syncthreads();
    {
        int tq = tid >> 4, tk = tid & 15;
        int tok0 = tq * 4, o0 = tk * 8;
        unsigned long long acc[4][4];
#pragma unroll
        for (int i = 0; i < 4; i++)
#pragma unroll
            for (int j = 0; j < 4; j++) acc[i][j] = 0ull;
#pragma unroll 4
        for (int f = 0; f < 64; f++) {
            float4 qv = *(const float4*)(qsT + f * BK_QT + tok0);
            ulonglong2 rA = *(const ulonglong2*)(rs + f * BK_RS + o0);
            ulonglong2 rB = *(const ulonglong2*)(rs + f * BK_RS + o0 + 4);
            unsigned long long qp[4], rp[4];
            qp[0] = pack2(qv.x, qv.x); qp[1] = pack2(qv.y, qv.y);
            qp[2] = pack2(qv.z, qv.z); qp[3] = pack2(qv.w, qv.w);
            rp[0] = rA.x; rp[1] = rA.y; rp[2] = rB.x; rp[3] = rB.y;
#pragma unroll
            for (int i = 0; i < 4; i++)
#pragma unroll
                for (int j = 0; j < 4; j++) fma2(acc[i][j], qp[i], rp[j]);
        }
#pragma unroll
        for (int i = 0; i < 4; i++)
#pragma unroll
            for (int j = 0; j < 4; j++) {
                float lo, hi;
                unpack2(acc[i][j], lo, hi);
                dt[(tok0 + i) * BK_RS + o0 + 2 * j] = lo;
                dt[(tok0 + i) * BK_RS + o0 + 2 * j + 1] = hi;
            }
    }
    __syncthreads();
#pragma unroll
    for (int rep = 0; rep < 2; rep++) {
        int pair = tid + rep * 256;
        int tok = pair >> 3, h = pair & 7;
        const float* row = dt + tok * BK_RS + h * 16;
        float a[16];
#pragma unroll
        for (int j = 0; j < 16; j++) a[j] = row[j];
        float best = a[0]; int bj = 0;
#pragma unroll
        for (int j = 1; j < 16; j++) if (a[j] > best) { best = a[j]; bj = j; }
#pragma unroll
        for (int j = 0; j < 16; j++) { float nv = -a[j]; if (nv > best) { best = nv; bj = 16 + j; } }
        bucket[(bh * NH_ + h) * T_ + t0 + tok] = bj;
    }
}

// ---------------- exact stable sort: warp-per-bucket ballot scan ----------------
__global__ void __launch_bounds__(1024) sort_kernel(const int* __restrict__ bucket,
                                                    int* __restrict__ st, int* __restrict__ sidx) {
    int h = blockIdx.x, bh = blockIdx.y;
    const int* bk = bucket + (bh * NH_ + h) * T_;
    int wid = threadIdx.x >> 5, lane = threadIdx.x & 31;
    __shared__ int pref[32];
    int cnt = 0;
    for (int i = 0; i < T_ / 32; i++) {
        int bb = bk[i * 32 + lane];
        unsigned mask = __ballot_sync(0xffffffffu, bb == wid);
        cnt += __popc(mask);
    }
    if (lane == 0) pref[wid] = cnt;
    __syncthreads();
    if (wid == 0) {
        int vv = pref[lane];
        int ex = vv;
        for (int o = 1; o < 32; o <<= 1) {
            int n = __shfl_up_sync(0xffffffffu, ex, o);
            if (lane >= o) ex += n;
        }
        pref[lane] = ex - vv;
    }
    __syncthreads();
    int base = bh * (NH_ * T_);
    int off = h * T_ + pref[wid];
    unsigned lt = (1u << lane) - 1u;
    for (int i = 0; i < T_ / 32; i++) {
        int p = i * 32 + lane;
        int bb = bk[p];
        unsigned mask = __ballot_sync(0xffffffffu, bb == wid);
        if (bb == wid) {
            int r = __popc(mask & lt);
            st[base + off + r] = p;
            sidx[base + h * T_ + p] = off + r;
        }
        off += __popc(mask);
    }
}

// ---------------- chunked attention: fused softmax + vectorized P@V ----------------
#define KST_STR 132
#define VS_STR  68
#define DOT_STR 132
#define ATT_SMEM ((64 * KST_STR + 128 * VS_STR + 64 * DOT_STR + 128 + 64) * 4 + 128 * 4)

__global__ void __launch_bounds__(256) attn2_kernel(const float* __restrict__ qk,
                                                    const float* __restrict__ v,
                                                    const int* __restrict__ st,
                                                    float* __restrict__ so,
                                                    float* __restrict__ sl) {
    int c = blockIdx.x;
    int bh = blockIdx.y;
    extern __shared__ float sm[];
    float* ksT  = sm;                          // [64][132] normalized K, f-major
    float* vs   = ksT + 64 * KST_STR;          // [128][68]
    float* dots = vs + 128 * VS_STR;           // [64][132]  exp(d - m)
    float* nrm  = dots + 64 * DOT_STR;         // [128]
    float* rcp  = nrm + 128;                   // [64]
    int*   pk   = (int*)(rcp + 64);            // [128]
    int tid = threadIdx.x;
    int b = bh >> 3, hd = bh & 7;
    int cp = (c + NCHUNK_ - 1) & (NCHUNK_ - 1);

    // --- stage: 2 threads per row, normalize K, copy V ---
    {
        int kk = tid >> 1, h = tid & 1;
        int cc = (kk < 64) ? c : cp;
        int p = st[bh * (NH_ * T_) + cc * 64 + (kk & 63)];
        if (!h) pk[kk] = p;
        const float* qr = qk + (size_t)(b * T_ + p) * DIM_ + hd * DH_ + h * 32;
        const float* vr = v  + (size_t)(b * T_ + p) * DIM_ + hd * DH_ + h * 32;
        float4 qv[8];
        float ss = 0.f;
#pragma unroll
        for (int i = 0; i < 8; i++) {
            qv[i] = *(const float4*)(qr + i * 4);
            ss += qv[i].x * qv[i].x + qv[i].y * qv[i].y + qv[i].z * qv[i].z + qv[i].w * qv[i].w;
        }
        float tot = ss + __shfl_xor_sync(0xffffffffu, ss, 1);
        float cl = fmaxf(sqrtf(tot), 1e-12f);
        if (!h) nrm[kk] = cl;
        float rn = 1.f / cl;
#pragma unroll
        for (int i = 0; i < 8; i++) {
            int f = h * 32 + i * 4;
            ksT[(f + 0) * KST_STR + kk] = qv[i].x * rn;
            ksT[(f + 1) * KST_STR + kk] = qv[i].y * rn;
            ksT[(f + 2) * KST_STR + kk] = qv[i].z * rn;
            ksT[(f + 3) * KST_STR + kk] = qv[i].w * rn;
            *(float4*)(vs + kk * VS_STR + f) = *(const float4*)(vr + i * 4);
        }
    }
    __syncthreads();

    // --- phase A: dots + fused mask/softmax (4q x 8k per thread, half-warp reduce) ---
    {
        int tq = tid >> 4, tk = tid & 15;
        int q0 = tq * 4, k0 = tk * 8;
        unsigned long long acc[4][4];
#pragma unroll
        for (int i = 0; i < 4; i++)
#pragma unroll
            for (int j = 0; j < 4; j++) acc[i][j] = 0ull;
#pragma unroll 4
        for (int f = 0; f < 64; f++) {
            const float* row = ksT + f * KST_STR;
            float4 qv = *(const float4*)(row + q0);
            ulonglong2 kA = *(const ulonglong2*)(row + k0);
            ulonglong2 kB = *(const ulonglong2*)(row + k0 + 4);
            unsigned long long qp[4], kp[4];
            qp[0] = pack2(qv.x, qv.x); qp[1] = pack2(qv.y, qv.y);
            qp[2] = pack2(qv.z, qv.z); qp[3] = pack2(qv.w, qv.w);
            kp[0] = kA.x; kp[1] = kA.y; kp[2] = kB.x; kp[3] = kB.y;
#pragma unroll
            for (int i = 0; i < 4; i++)
#pragma unroll
                for (int j = 0; j < 4; j++) fma2(acc[i][j], qp[i], kp[j]);
        }
        int pks[8];
#pragma unroll
        for (int j = 0; j < 8; j++) pks[j] = pk[k0 + j];
#pragma unroll
        for (int i = 0; i < 4; i++) {
            float d[8];
#pragma unroll
            for (int j = 0; j < 4; j++) unpack2(acc[i][j], d[2 * j], d[2 * j + 1]);
            float sc = nrm[q0 + i] * 0.125f;
            int pq = pk[q0 + i];
            float mx = -INFINITY;
#pragma unroll
            for (int j = 0; j < 8; j++) {
                d[j] = (pks[j] == pq) ? -5e4f : d[j] * sc;
                mx = fmaxf(mx, d[j]);
            }
            mx = fmaxf(mx, __shfl_xor_sync(0xffffffffu, mx, 1));
            mx = fmaxf(mx, __shfl_xor_sync(0xffffffffu, mx, 2));
            mx = fmaxf(mx, __shfl_xor_sync(0xffffffffu, mx, 4));
            mx = fmaxf(mx, __shfl_xor_sync(0xffffffffu, mx, 8));
            float ss = 0.f;
#pragma unroll
            for (int j = 0; j < 8; j++) {
                d[j] = expf(d[j] - mx);
                ss += d[j];
            }
            ss += __shfl_xor_sync(0xffffffffu, ss, 1);
            ss += __shfl_xor_sync(0xffffffffu, ss, 2);
            ss += __shfl_xor_sync(0xffffffffu, ss, 4);
            ss += __shfl_xor_sync(0xffffffffu, ss, 8);
            float* dr = dots + (q0 + i) * DOT_STR + k0;
            *(float4*)dr = make_float4(d[0], d[1], d[2], d[3]);
            *(float4*)(dr + 4) = make_float4(d[4], d[5], d[6], d[7]);
            if (tk == 0) {
                rcp[q0 + i] = 1.f / ss;
                sl[bh * (NH_ * T_) + c * 64 + q0 + i] = mx + logf(ss);
            }
        }
    }
    __syncthreads();

    // --- phase C: out(64x64) = P(64x128) @ V(128x64), vectorized P loads ---
    {
        int tq = tid >> 4, tf = tid & 15;
        int q0 = tq * 4, f0 = tf * 4;
        unsigned long long acc[4][2];
#pragma unroll
        for (int i = 0; i < 4; i++) { acc[i][0] = 0ull; acc[i][1] = 0ull; }
        for (int kk4 = 0; kk4 < 128; kk4 += 4) {
            float4 pv[4];
#pragma unroll
            for (int i = 0; i < 4; i++)
                pv[i] = *(const float4*)(dots + (q0 + i) * DOT_STR + kk4);
#pragma unroll
            for (int j = 0; j < 4; j++) {
                ulonglong2 vv = *(const ulonglong2*)(vs + (kk4 + j) * VS_STR + f0);
                float pj[4] = {
                    (j == 0) ? pv[0].x : (j == 1) ? pv[0].y : (j == 2) ? pv[0].z : pv[0].w,
                    (j == 0) ? pv[1].x : (j == 1) ? pv[1].y : (j == 2) ? pv[1].z : pv[1].w,
                    (j == 0) ? pv[2].x : (j == 1) ? pv[2].y : (j == 2) ? pv[2].z : pv[2].w,
                    (j == 0) ? pv[3].x : (j == 1) ? pv[3].y : (j == 2) ? pv[3].z : pv[3].w
                };
#pragma unroll
                for (int i = 0; i < 4; i++) {
                    unsigned long long pp = pack2(pj[i], pj[i]);
                    fma2(acc[i][0], pp, vv.x);
                    fma2(acc[i][1], pp, vv.y);
                }
            }
        }
#pragma unroll
        for (int i = 0; i < 4; i++) {
            float r = rcp[q0 + i];
            size_t base = ((size_t)bh * (NH_ * T_) + c * 64 + q0 + i) * DH_ + f0;
#pragma unroll
            for (int j = 0; j < 2; j++) {
                float lo, hi;
                unpack2(acc[i][j], lo, hi);
                float2 o2 = make_float2(lo * r, hi * r);
                *(float2*)(so + base + 2 * j) = o2;
            }
        }
    }
}

// ---------------- combine hash rounds ----------------
__global__ void __launch_bounds__(256) combine_kernel(const float* __restrict__ so,
                                                      const float* __restrict__ sl,
                                                      const int* __restrict__ sidx,
                                                      float* __restrict__ attn) {
    int t = blockIdx.x * 4 + (threadIdx.x >> 6);
    int bh = blockIdx.y;
    int f = threadIdx.x & 63;
    int b = bh >> 3, hd = bh & 7;
    int sbase = bh * (NH_ * T_);
    int sarr[NH_]; float lg[NH_];
    float m = -INFINITY;
#pragma unroll
    for (int h = 0; h < NH_; h++) {
        int s = sidx[sbase + h * T_ + t];
        sarr[h] = s;
        lg[h] = sl[sbase + s];
        m = fmaxf(m, lg[h]);
    }
    float den = 0.f;
#pragma unroll
    for (int h = 0; h < NH_; h++) den += expf(lg[h] - m);
    float out = 0.f;
#pragma unroll
    for (int h = 0; h < NH_; h++)
        out += (expf(lg[h] - m) / den) * so[((size_t)sbase + sarr[h]) * DH_ + f];
    attn[(b * T_ + t) * DIM_ + hd * DH_ + f] = out;
}

// ---------------- y = 0.5*(x1+x2) ----------------
__global__ void avg_kernel(const float* __restrict__ x1, const float* __restrict__ x2,
                           float* __restrict__ y, int n) {
    int i = blockIdx.x * blockDim.x + threadIdx.x;
    if (i < n) y[i] = 0.5f * (x1[i] + x2[i]);
}

// ---------------- host orchestration ----------------
static float* sym_f(const void* s) { void* p = nullptr; cudaGetSymbolAddress(&p, s); return (float*)p; }
static int*   sym_i(const void* s) { void* p = nullptr; cudaGetSymbolAddress(&p, s); return (int*)p; }

extern "C" void kernel_launch(void* const* d_in, const int* in_sizes, int n_in,
                              void* d_out, int out_size) {
    const float* spec   = (const float*)d_in[0];
    const float* conv_w = (const float*)d_in[1];
    const float* conv_b = (const float*)d_in[2];
    const float* pe_row = (const float*)d_in[3];
    const float* pe_col = (const float*)d_in[4];
    const float* lnA_g  = (const float*)d_in[5];
    const float* lnA_b  = (const float*)d_in[6];
    const float* wqk    = (const float*)d_in[7];
    const float* wv     = (const float*)d_in[8];
    const float* wo     = (const float*)d_in[9];
    const float* bo     = (const float*)d_in[10];
    const float* lnF_g  = (const float*)d_in[11];
    const float* lnF_b  = (const float*)d_in[12];
    const float* w1     = (const float*)d_in[13];
    const float* b1     = (const float*)d_in[14];
    const float* w2     = (const float*)d_in[15];
    const float* b2     = (const float*)d_in[16];
    const float* lin_w  = (const float*)d_in[17];
    const float* lin_b  = (const float*)d_in[18];
    const float* rot    = (const float*)d_in[19];
    float* out = (float*)d_out;

    float* x1   = sym_f(g_x1);
    float* x2   = sym_f(g_x2);
    float* xn   = sym_f(g_xn);
    float* qkb  = sym_f(g_qk);
    float* vb   = sym_f(g_v);
    float* attn = sym_f(g_attn);
    float* ffn  = sym_f(g_ffn);
    float* yb   = sym_f(g_y);
    float* so   = sym_f(g_so);
    float* sl   = sym_f(g_sl);
    int* bucket = sym_i(g_bucket);
    int* st     = sym_i(g_st);
    int* sidx   = sym_i(g_sidx);

    cudaFuncSetAttribute(attn2_kernel, cudaFuncAttributeMaxDynamicSharedMemorySize, ATT_SMEM);
    cudaFuncSetAttribute(bucket_kernel, cudaFuncAttributeMaxDynamicSharedMemorySize, BKT_SMEM);

    // frontend
    conv_pe_kernel<<<dim3(T_, B_), 256>>>(spec, conv_w, conv_b, pe_row, pe_col, x1, x2);

    dim3 gQKV(DIM_ / 128, ROWS_ / 128, 2);
    dim3 g512(DIM_ / 128, ROWS_ / 128, 1);
    dim3 gffn(FFN_ / 128, ROWS_ / 128, 1);
    dim3 gout((NPITCH_ + 63) / 64, ROWS_ / 64);

    for (int l = 0; l < DEPTH_; l++) {
        const float* Wqk = wqk + (size_t)l * DIM_ * DIM_;
        const float* Wv  = wv  + (size_t)l * DIM_ * DIM_;
        const float* Wo  = wo  + (size_t)l * DIM_ * DIM_;
        const float* Bo  = bo  + (size_t)l * DIM_;
        const float* W1  = w1  + (size_t)l * DIM_ * FFN_;
        const float* B1  = b1  + (size_t)l * FFN_;
        const float* W2  = w2  + (size_t)l * DIM_ * FFN_;
        const float* B2  = b2  + (size_t)l * DIM_;
        const float* rotL = rot + (size_t)l * DH_ * NH_ * 16;

        // attention branch
        ln_kernel<<<ROWS_ / 8, 256>>>(x2, lnA_g + l * DIM_, lnA_b + l * DIM_, xn);
        sgemm128_kernel<<<gQKV, 256>>>(xn, Wqk, nullptr, qkb, Wv, vb, DIM_, DIM_, 0, 0);
        bucket_kernel<<<dim3(T_ / 64, BH_), 256, BKT_SMEM>>>(qkb, rotL, bucket);
        sort_kernel<<<dim3(NH_, BH_), 1024>>>(bucket, st, sidx);
        attn2_kernel<<<dim3(NCHUNK_, BH_), 256, ATT_SMEM>>>(qkb, vb, st, so, sl);
        combine_kernel<<<dim3(T_ / 4, BH_), 256>>>(so, sl, sidx, attn);
        sgemm128_kernel<<<g512, 256>>>(attn, Wo, Bo, x1, nullptr, nullptr, DIM_, DIM_, 0, 1);

        // ffn branch
        ln_kernel<<<ROWS_ / 8, 256>>>(x1, lnF_g + l * DIM_, lnF_b + l * DIM_, xn);
        sgemm128_kernel<<<gffn, 256>>>(xn, W1, B1, ffn, nullptr, nullptr, FFN_, DIM_, 2, 0);
        sgemm128_kernel<<<g512, 256>>>(ffn, W2, B2, x2, nullptr, nullptr, DIM_, FFN_, 0, 1);
    }

    avg_kernel<<<(ROWS_ * DIM_ + 255) / 256, 256>>>(x1, x2, yb, ROWS_ * DIM_);
    sgemm_kernel<<<gout, 256>>>(yb, lin_w, lin_b, out, ROWS_, NPITCH_, DIM_, 0, 0);
}

// round 17
// speedup vs baseline: 1.1321x; 1.0109x over previous
#include <cuda_runtime.h>
#include <cuda_bf16.h>
#include <math.h>

// ---------------- problem constants ----------------
#define B_      2
#define T_      2048
#define DIM_    512
#define HEADS_  8
#define DH_     64
#define NH_     8
#define NB_     32
#define BUCKET_ 64
#define NCHUNK_ 256
#define BH_     16
#define ROWS_   4096
#define SPEC_   229
#define DEPTH_  8
#define NPITCH_ 88
#define FFN_    2048

// ---------------- packed fp32x2 helpers (sm_100+) ----------------
__device__ __forceinline__ unsigned long long pack2(float lo, float hi) {
    unsigned long long r;
    asm("mov.b64 %0, {%1, %2};" : "=l"(r) : "f"(lo), "f"(hi));
    return r;
}
__device__ __forceinline__ void unpack2(unsigned long long p, float& lo, float& hi) {
    asm("mov.b64 {%0, %1}, %2;" : "=f"(lo), "=f"(hi) : "l"(p));
}
__device__ __forceinline__ void fma2(unsigned long long& c, unsigned long long a, unsigned long long b) {
    asm("fma.rn.f32x2 %0, %1, %2, %0;" : "+l"(c) : "l"(a), "l"(b));
}

// ---------------- scratch (device globals; no allocation allowed) ----------------
__device__ float g_x1[ROWS_ * DIM_];
__device__ float g_x2[ROWS_ * DIM_];
__device__ float g_xn[ROWS_ * DIM_];
__device__ float g_qk[ROWS_ * DIM_];
__device__ float g_v [ROWS_ * DIM_];
__device__ float g_attn[ROWS_ * DIM_];
__device__ float g_ffn[ROWS_ * FFN_];
__device__ float g_y [ROWS_ * DIM_];
__device__ int   g_bucket[BH_ * NH_ * T_];
__device__ int   g_st  [BH_ * NH_ * T_];
__device__ int   g_sidx[BH_ * NH_ * T_];
__device__ float g_so  [BH_ * NH_ * T_ * DH_];
__device__ float g_sl  [BH_ * NH_ * T_];

// ---------------- conv frontend + positional embedding ----------------
__global__ void conv_pe_kernel(const float* __restrict__ spec,
                               const float* __restrict__ w,
                               const float* __restrict__ cb,
                               const float* __restrict__ pe_row,
                               const float* __restrict__ pe_col,
                               float* __restrict__ x1, float* __restrict__ x2) {
    int t = blockIdx.x, b = blockIdx.y;
    __shared__ float s[3 * SPEC_];
    int tid = threadIdx.x;
    for (int i = tid; i < 3 * SPEC_; i += 256) {
        int k = i / SPEC_, ii = i % SPEC_;
        int tt = t + k - 1;
        s[i] = (tt >= 0 && tt < T_) ? spec[(b * T_ + tt) * SPEC_ + ii] : 0.f;
    }
    __syncthreads();
    int r = b * T_ + t;
    for (int o = tid; o < DIM_; o += 256) {
        float acc = cb[o];
        const float* wo_ = w + o * SPEC_ * 3;
        for (int i = 0; i < SPEC_; i++) {
            float w0 = wo_[i * 3 + 0], w1 = wo_[i * 3 + 1], w2 = wo_[i * 3 + 2];
            acc += s[i] * w0 + s[SPEC_ + i] * w1 + s[2 * SPEC_ + i] * w2;
        }
        acc = fmaxf(acc, 0.f);
        float pe = (o < 256) ? pe_row[(t >> 6) * 256 + o]
                             : pe_col[(t & 63) * 256 + (o - 256)];
        acc += pe;
        x1[r * DIM_ + o] = acc;
        x2[r * DIM_ + o] = acc;
    }
}

// ---------------- layernorm: warp per row ----------------
__global__ void __launch_bounds__(256) ln_kernel(const float* __restrict__ x,
                                                 const float* __restrict__ g,
                                                 const float* __restrict__ bt,
                                                 float* __restrict__ y) {
    int warp = threadIdx.x >> 5, lane = threadIdx.x & 31;
    int r = blockIdx.x * 8 + warp;
    const float4* xr = (const float4*)(x + (size_t)r * DIM_);
    float4 v[4];
    float sum = 0.f, sq = 0.f;
#pragma unroll
    for (int i = 0; i < 4; i++) {
        v[i] = xr[lane + 32 * i];
        sum += v[i].x + v[i].y + v[i].z + v[i].w;
        sq += v[i].x * v[i].x + v[i].y * v[i].y + v[i].z * v[i].z + v[i].w * v[i].w;
    }
#pragma unroll
    for (int o = 16; o > 0; o >>= 1) {
        sum += __shfl_xor_sync(0xffffffffu, sum, o);
        sq  += __shfl_xor_sync(0xffffffffu, sq, o);
    }
    float mean = sum * (1.f / DIM_);
    float var = fmaxf(sq * (1.f / DIM_) - mean * mean, 0.f);
    float rstd = rsqrtf(var + 1e-5f);
    float4* yr = (float4*)(y + (size_t)r * DIM_);
#pragma unroll
    for (int i = 0; i < 4; i++) {
        int c = (lane + 32 * i) * 4;
        float4 gg = *(const float4*)(g + c);
        float4 bb = *(const float4*)(bt + c);
        float4 o;
        o.x = (v[i].x - mean) * rstd * gg.x + bb.x;
        o.y = (v[i].y - mean) * rstd * gg.y + bb.y;
        o.z = (v[i].z - mean) * rstd * gg.z + bb.z;
        o.w = (v[i].w - mean) * rstd * gg.w + bb.w;
        yr[lane + 32 * i] = o;
    }
}

// ---------------- big SGEMM (R8 proven): 128x128x16, 8x8/thread, f32x2 ----------------
__global__ void __launch_bounds__(256, 2) sgemm128_kernel(
    const float* __restrict__ A, const float* __restrict__ Bm,
    const float* __restrict__ bias, float* __restrict__ C,
    const float* __restrict__ Bm2, float* __restrict__ C2,
    int N, int K, int act, int acc) {
    if (blockIdx.z == 1) { Bm = Bm2; C = C2; }
    __shared__ __align__(16) float As[2][16][132];
    __shared__ __align__(16) float Bs[2][16][132];
    int m0 = blockIdx.y * 128, n0 = blockIdx.x * 128;
    int tid = threadIdx.x;
    int a_r = tid >> 2, a_c = (tid & 3) << 2;
    int b_r = tid >> 5, b_c = (tid & 31) << 2;
    int tr = tid >> 4, tc = tid & 15;
    int r0 = tr * 4, c0 = tc * 4;
    unsigned long long accp[8][4];
#pragma unroll
    for (int i = 0; i < 8; i++)
#pragma unroll
        for (int j = 0; j < 4; j++) accp[i][j] = 0ull;

    const float* Ap0 = A + (size_t)(m0 + a_r) * K + a_c;
    const float* Ap1 = A + (size_t)(m0 + a_r + 64) * K + a_c;
    const float* Bp0 = Bm + (size_t)b_r * N + n0 + b_c;
    const float* Bp1 = Bm + (size_t)(b_r + 8) * N + n0 + b_c;

    float4 a0 = *(const float4*)(Ap0);
    float4 a1 = *(const float4*)(Ap1);
    float4 b0 = *(const float4*)(Bp0);
    float4 b1 = *(const float4*)(Bp1);
    As[0][a_c + 0][a_r] = a0.x; As[0][a_c + 1][a_r] = a0.y;
    As[0][a_c + 2][a_r] = a0.z; As[0][a_c + 3][a_r] = a0.w;
    As[0][a_c + 0][a_r + 64] = a1.x; As[0][a_c + 1][a_r + 64] = a1.y;
    As[0][a_c + 2][a_r + 64] = a1.z; As[0][a_c + 3][a_r + 64] = a1.w;
    *(float4*)&Bs[0][b_r][b_c] = b0;
    *(float4*)&Bs[0][b_r + 8][b_c] = b1;
    __syncthreads();

    int cur = 0;
    for (int k0 = 0; k0 < K; k0 += 16) {
        bool more = (k0 + 16) < K;
        if (more) {
            a0 = *(const float4*)(Ap0 + k0 + 16);
            a1 = *(const float4*)(Ap1 + k0 + 16);
            b0 = *(const float4*)(Bp0 + (size_t)(k0 + 16) * N);
            b1 = *(const float4*)(Bp1 + (size_t)(k0 + 16) * N);
        }
#pragma unroll
        for (int k = 0; k < 16; k++) {
            float4 aA = *(const float4*)&As[cur][k][r0];
            float4 aB = *(const float4*)&As[cur][k][r0 + 64];
            ulonglong2 bA = *(const ulonglong2*)&Bs[cur][k][c0];
            ulonglong2 bB = *(const ulonglong2*)&Bs[cur][k][c0 + 64];
            unsigned long long ap[8], bp[4];
            ap[0] = pack2(aA.x, aA.x); ap[1] = pack2(aA.y, aA.y);
            ap[2] = pack2(aA.z, aA.z); ap[3] = pack2(aA.w, aA.w);
            ap[4] = pack2(aB.x, aB.x); ap[5] = pack2(aB.y, aB.y);
            ap[6] = pack2(aB.z, aB.z); ap[7] = pack2(aB.w, aB.w);
            bp[0] = bA.x; bp[1] = bA.y; bp[2] = bB.x; bp[3] = bB.y;
#pragma unroll
            for (int i = 0; i < 8; i++)
#pragma unroll
                for (int j = 0; j < 4; j++) fma2(accp[i][j], ap[i], bp[j]);
        }
        if (more) {
            int nxt = cur ^ 1;
            As[nxt][a_c + 0][a_r] = a0.x; As[nxt][a_c + 1][a_r] = a0.y;
            As[nxt][a_c + 2][a_r] = a0.z; As[nxt][a_c + 3][a_r] = a0.w;
            As[nxt][a_c + 0][a_r + 64] = a1.x; As[nxt][a_c + 1][a_r + 64] = a1.y;
            As[nxt][a_c + 2][a_r + 64] = a1.z; As[nxt][a_c + 3][a_r + 64] = a1.w;
            *(float4*)&Bs[nxt][b_r][b_c] = b0;
            *(float4*)&Bs[nxt][b_r + 8][b_c] = b1;
            __syncthreads();
            cur = nxt;
        }
    }
#pragma unroll
    for (int i = 0; i < 8; i++) {
        int m = m0 + ((i < 4) ? (r0 + i) : (64 + r0 + i - 4));
#pragma unroll
        for (int j = 0; j < 4; j++) {
            float lo, hi;
            unpack2(accp[i][j], lo, hi);
            int n = n0 + ((j < 2) ? (c0 + 2 * j) : (64 + c0 + 2 * (j - 2)));
            float v0 = lo + (bias ? bias[n] : 0.f);
            float v1 = hi + (bias ? bias[n + 1] : 0.f);
            if (act == 2) {
                v0 = 0.5f * v0 * (1.f + erff(v0 * 0.70710678118654752f));
                v1 = 0.5f * v1 * (1.f + erff(v1 * 0.70710678118654752f));
            }
            float* p = C + (size_t)m * N + n;
            if (acc) { p[0] += v0; p[1] += v1; }
            else     { p[0] = v0;  p[1] = v1; }
        }
    }
}

// ---------------- small SGEMM (N=88 final projection, optional A2 for avg fusion) ----------------
__global__ void sgemm_kernel(const float* __restrict__ A, const float* __restrict__ B,
                             const float* __restrict__ bias, float* __restrict__ C,
                             const float* __restrict__ A2,
                             int M, int N, int K, int act, int acc) {
    __shared__ float As[16][65];
    __shared__ float Bs[16][65];
    int m0 = blockIdx.y * 64, n0 = blockIdx.x * 64;
    int tid = threadIdx.x;
    int tc = tid & 15, tr = tid >> 4;
    int a_r = tid >> 2, a_c0 = (tid & 3) * 4;
    int b_r = tid >> 4, b_c0 = (tid & 15) * 4;
    float accv[4][4] = {};
    for (int k0 = 0; k0 < K; k0 += 16) {
        const float* Ap = A + (size_t)(m0 + a_r) * K + k0 + a_c0;
        const float* Ap2 = A2 ? A2 + (size_t)(m0 + a_r) * K + k0 + a_c0 : nullptr;
#pragma unroll
        for (int j = 0; j < 4; j++)
            As[a_c0 + j][a_r] = Ap2 ? 0.5f * (Ap[j] + Ap2[j]) : Ap[j];
#pragma unroll
        for (int j = 0; j < 4; j++) {
            int n = n0 + b_c0 + j;
            Bs[b_r][b_c0 + j] = (n < N) ? B[(k0 + b_r) * N + n] : 0.f;
        }
        __syncthreads();
#pragma unroll
        for (int k = 0; k < 16; k++) {
            float av[4], bv[4];
#pragma unroll
            for (int i = 0; i < 4; i++) av[i] = As[k][tr * 4 + i];
#pragma unroll
            for (int j = 0; j < 4; j++) bv[j] = Bs[k][tc * 4 + j];
#pragma unroll
            for (int i = 0; i < 4; i++)
#pragma unroll
                for (int j = 0; j < 4; j++) accv[i][j] += av[i] * bv[j];
        }
        __syncthreads();
    }
#pragma unroll
    for (int i = 0; i < 4; i++) {
        int m = m0 + tr * 4 + i;
#pragma unroll
        for (int j = 0; j < 4; j++) {
            int n = n0 + tc * 4 + j;
            if (n < N) {
                float val = accv[i][j] + (bias ? bias[n] : 0.f);
                if (act == 2) val = 0.5f * val * (1.f + erff(val * 0.70710678118654752f));
                C[m * N + n] = acc ? (C[m * N + n] + val) : val;
            }
        }
    }
}

// ---------------- LSH bucketing: GEMM tile in regs, dt overlays rs ----------------
#define BK_QT 68
#define BK_RS 132
#define BKT_SMEM ((64 * BK_QT + 64 * BK_RS) * 4)
__global__ void __launch_bounds__(256) bucket_kernel(const float* __restrict__ qk,
                                                     const float* __restrict__ rotL,
                                                     int* __restrict__ bucket) {
    extern __shared__ float bsm[];
    float* qsT = bsm;                    // [64 f][68 tok]
    float* rs  = qsT + 64 * BK_QT;       // [64 f][132 out]  (becomes dt after GEMM)
    int tid = threadIdx.x;
    int bh = blockIdx.y;
    int b = bh >> 3, hd = bh & 7;
    int t0 = blockIdx.x * 64;
#pragma unroll
    for (int it = 0; it < 4; it++) {
        int lin = tid + it * 256;
        int tok = lin >> 4, c4 = (lin & 15) << 2;
        float4 qv = *(const float4*)(qk + (size_t)(b * T_ + t0 + tok) * DIM_ + hd * DH_ + c4);
        qsT[(c4 + 0) * BK_QT + tok] = qv.x;
        qsT[(c4 + 1) * BK_QT + tok] = qv.y;
        qsT[(c4 + 2) * BK_QT + tok] = qv.z;
        qsT[(c4 + 3) * BK_QT + tok] = qv.w;
    }
#pragma unroll
    for (int it = 0; it < 8; it++) {
        int lin = tid + it * 256;
        int f = lin >> 5, c4 = (lin & 31) << 2;
        *(float4*)(rs + f * BK_RS + c4) = *(const float4*)(rotL + f * 128 + c4);
    }
    __syncthreads();
    int tq = tid >> 4, tk = tid & 15;
    int tok0 = tq * 4, o0 = tk * 8;
    unsigned long long acc[4][4];
#pragma unroll
    for (int i = 0; i < 4; i++)
#pragma unroll
        for (int j = 0; j < 4; j++) acc[i][j] = 0ull;
#pragma unroll 4
    for (int f = 0; f < 64; f++) {
        float4 qv = *(const float4*)(qsT + f * BK_QT + tok0);
        ulonglong2 rA = *(const ulonglong2*)(rs + f * BK_RS + o0);
        ulonglong2 rB = *(const ulonglong2*)(rs + f * BK_RS + o0 + 4);
        unsigned long long qp[4], rp[4];
        qp[0] = pack2(qv.x, qv.x); qp[1] = pack2(qv.y, qv.y);
        qp[2] = pack2(qv.z, qv.z); qp[3] = pack2(qv.w, qv.w);
        rp[0] = rA.x; rp[1] = rA.y; rp[2] = rB.x; rp[3] = rB.y;
#pragma unroll
        for (int i = 0; i < 4; i++)
#pragma unroll
            for (int j = 0; j < 4; j++) fma2(acc[i][j], qp[i], rp[j]);
    }
    __syncthreads();                      // all rs reads done
    float* dt = rs;                       // overlay
#pragma unroll
    for (int i = 0; i < 4; i++)
#pragma unroll
        for (int j = 0; j < 4; j++) {
            float lo, hi;
            unpack2(acc[i][j], lo, hi);
            dt[(tok0 + i) * BK_RS + o0 + 2 * j] = lo;
            dt[(tok0 + i) * BK_RS + o0 + 2 * j + 1] = hi;
        }
    __syncthreads();
#pragma unroll
    for (int rep = 0; rep < 2; rep++) {
        int pair = tid + rep * 256;
        int tok = pair >> 3, h = pair & 7;
        const float* row = dt + tok * BK_RS + h * 16;
        float a[16];
#pragma unroll
        for (int j = 0; j < 16; j++) a[j] = row[j];
        float best = a[0]; int bj = 0;
#pragma unroll
        for (int j = 1; j < 16; j++) if (a[j] > best) { best = a[j]; bj = j; }
#pragma unroll
        for (int j = 0; j < 16; j++) { float nv = -a[j]; if (nv > best) { best = nv; bj = 16 + j; } }
        bucket[(bh * NH_ + h) * T_ + t0 + tok] = bj;
    }
}

// ---------------- exact stable sort: warp-per-bucket ballot scan ----------------
__global__ void __launch_bounds__(1024) sort_kernel(const int* __restrict__ bucket,
                                                    int* __restrict__ st, int* __restrict__ sidx) {
    int h = blockIdx.x, bh = blockIdx.y;
    const int* bk = bucket + (bh * NH_ + h) * T_;
    int wid = threadIdx.x >> 5, lane = threadIdx.x & 31;
    __shared__ int pref[32];
    int cnt = 0;
    for (int i = 0; i < T_ / 32; i++) {
        int bb = bk[i * 32 + lane];
        unsigned mask = __ballot_sync(0xffffffffu, bb == wid);
        cnt += __popc(mask);
    }
    if (lane == 0) pref[wid] = cnt;
    __syncthreads();
    if (wid == 0) {
        int vv = pref[lane];
        int ex = vv;
        for (int o = 1; o < 32; o <<= 1) {
            int n = __shfl_up_sync(0xffffffffu, ex, o);
            if (lane >= o) ex += n;
        }
        pref[lane] = ex - vv;
    }
    __syncthreads();
    int base = bh * (NH_ * T_);
    int off = h * T_ + pref[wid];
    unsigned lt = (1u << lane) - 1u;
    for (int i = 0; i < T_ / 32; i++) {
        int p = i * 32 + lane;
        int bb = bk[p];
        unsigned mask = __ballot_sync(0xffffffffu, bb == wid);
        if (bb == wid) {
            int r = __popc(mask & lt);
            st[base + off + r] = p;
            sidx[base + h * T_ + p] = off + r;
        }
        off += __popc(mask);
    }
}

// ---------------- chunked attention: smem overlay (dots reuses ksT), 3 blocks/SM ----------------
#define KST_STR 132
#define VS_STR  68
#define ATT_SMEM ((64 * KST_STR + 128 * VS_STR + 128) * 4 + 128 * 4)

__global__ void __launch_bounds__(256) attn2_kernel(const float* __restrict__ qk,
                                                    const float* __restrict__ v,
                                                    const int* __restrict__ st,
                                                    float* __restrict__ so,
                                                    float* __restrict__ sl) {
    int c = blockIdx.x;
    int bh = blockIdx.y;
    extern __shared__ float sm[];
    float* ksT  = sm;                          // [64][132] K^T; becomes dots (p/ss) after phase A
    float* vs   = ksT + 64 * KST_STR;          // [128][68]
    float* nrm  = vs + 128 * VS_STR;           // [128]
    int*   pk   = (int*)(nrm + 128);           // [128]
    int tid = threadIdx.x;
    int b = bh >> 3, hd = bh & 7;
    int cp = (c + NCHUNK_ - 1) & (NCHUNK_ - 1);

    // --- stage: 2 threads per row, normalize K, copy V ---
    {
        int kk = tid >> 1, h = tid & 1;
        int cc = (kk < 64) ? c : cp;
        int p = st[bh * (NH_ * T_) + cc * 64 + (kk & 63)];
        if (!h) pk[kk] = p;
        const float* qr = qk + (size_t)(b * T_ + p) * DIM_ + hd * DH_ + h * 32;
        const float* vr = v  + (size_t)(b * T_ + p) * DIM_ + hd * DH_ + h * 32;
        float4 qv[8];
        float ss = 0.f;
#pragma unroll
        for (int i = 0; i < 8; i++) {
            qv[i] = *(const float4*)(qr + i * 4);
            ss += qv[i].x * qv[i].x + qv[i].y * qv[i].y + qv[i].z * qv[i].z + qv[i].w * qv[i].w;
        }
        float tot = ss + __shfl_xor_sync(0xffffffffu, ss, 1);
        float cl = fmaxf(sqrtf(tot), 1e-12f);
        if (!h) nrm[kk] = cl;
        float rn = 1.f / cl;
#pragma unroll
        for (int i = 0; i < 8; i++) {
            int f = h * 32 + i * 4;
            ksT[(f + 0) * KST_STR + kk] = qv[i].x * rn;
            ksT[(f + 1) * KST_STR + kk] = qv[i].y * rn;
            ksT[(f + 2) * KST_STR + kk] = qv[i].z * rn;
            ksT[(f + 3) * KST_STR + kk] = qv[i].w * rn;
            *(float4*)(vs + kk * VS_STR + f) = *(const float4*)(vr + i * 4);
        }
    }
    __syncthreads();

    int tq = tid >> 4, tk = tid & 15;
    int q0 = tq * 4, k0 = tk * 8;

    // --- phase A: dots in registers + fused softmax; result repacked into acc ---
    unsigned long long acc[4][4];
    {
#pragma unroll
        for (int i = 0; i < 4; i++)
#pragma unroll
            for (int j = 0; j < 4; j++) acc[i][j] = 0ull;
#pragma unroll 4
        for (int f = 0; f < 64; f++) {
            const float* row = ksT + f * KST_STR;
            float4 qv = *(const float4*)(row + q0);
            ulonglong2 kA = *(const ulonglong2*)(row + k0);
            ulonglong2 kB = *(const ulonglong2*)(row + k0 + 4);
            unsigned long long qp[4], kp[4];
            qp[0] = pack2(qv.x, qv.x); qp[1] = pack2(qv.y, qv.y);
            qp[2] = pack2(qv.z, qv.z); qp[3] = pack2(qv.w, qv.w);
            kp[0] = kA.x; kp[1] = kA.y; kp[2] = kB.x; kp[3] = kB.y;
#pragma unroll
            for (int i = 0; i < 4; i++)
#pragma unroll
                for (int j = 0; j < 4; j++) fma2(acc[i][j], qp[i], kp[j]);
        }
        int pks[8];
#pragma unroll
        for (int j = 0; j < 8; j++) pks[j] = pk[k0 + j];
#pragma unroll
        for (int i = 0; i < 4; i++) {
            float d[8];
#pragma unroll
            for (int j = 0; j < 4; j++) unpack2(acc[i][j], d[2 * j], d[2 * j + 1]);
            float sc = nrm[q0 + i] * 0.125f;
            int pq = pk[q0 + i];
            float mx = -INFINITY;
#pragma unroll
            for (int j = 0; j < 8; j++) {
                d[j] = (pks[j] == pq) ? -5e4f : d[j] * sc;
                mx = fmaxf(mx, d[j]);
            }
            mx = fmaxf(mx, __shfl_xor_sync(0xffffffffu, mx, 1));
            mx = fmaxf(mx, __shfl_xor_sync(0xffffffffu, mx, 2));
            mx = fmaxf(mx, __shfl_xor_sync(0xffffffffu, mx, 4));
            mx = fmaxf(mx, __shfl_xor_sync(0xffffffffu, mx, 8));
            float ss = 0.f;
#pragma unroll
            for (int j = 0; j < 8; j++) {
                d[j] = expf(d[j] - mx);
                ss += d[j];
            }
            ss += __shfl_xor_sync(0xffffffffu, ss, 1);
            ss += __shfl_xor_sync(0xffffffffu, ss, 2);
            ss += __shfl_xor_sync(0xffffffffu, ss, 4);
            ss += __shfl_xor_sync(0xffffffffu, ss, 8);
            float rinv = 1.f / ss;
#pragma unroll
            for (int j = 0; j < 4; j++)
                acc[i][j] = pack2(d[2 * j] * rinv, d[2 * j + 1] * rinv);
            if (tk == 0)
                sl[bh * (NH_ * T_) + c * 64 + q0 + i] = mx + logf(ss);
        }
    }
    __syncthreads();                       // all ksT reads complete

    // --- write p/ss into the (dead) ksT region ---
    float* dots = ksT;
    {
#pragma unroll
        for (int i = 0; i < 4; i++) {
            float d[8];
#pragma unroll
            for (int j = 0; j < 4; j++) unpack2(acc[i][j], d[2 * j], d[2 * j + 1]);
            float* dr = dots + (q0 + i) * KST_STR + k0;
            *(float4*)dr = make_float4(d[0], d[1], d[2], d[3]);
            *(float4*)(dr + 4) = make_float4(d[4], d[5], d[6], d[7]);
        }
    }
    __syncthreads();

    // --- phase C: out(64x64) = P(64x128) @ V(128x64) ---
    {
        int tf = tk;
        int f0 = tf * 4;
        unsigned long long oacc[4][2];
#pragma unroll
        for (int i = 0; i < 4; i++) { oacc[i][0] = 0ull; oacc[i][1] = 0ull; }
        for (int kk4 = 0; kk4 < 128; kk4 += 4) {
            float4 pv[4];
#pragma unroll
            for (int i = 0; i < 4; i++)
                pv[i] = *(const float4*)(dots + (q0 + i) * KST_STR + kk4);
#pragma unroll
            for (int j = 0; j < 4; j++) {
                ulonglong2 vv = *(const ulonglong2*)(vs + (kk4 + j) * VS_STR + f0);
                float pj[4] = {
                    (j == 0) ? pv[0].x : (j == 1) ? pv[0].y : (j == 2) ? pv[0].z : pv[0].w,
                    (j == 0) ? pv[1].x : (j == 1) ? pv[1].y : (j == 2) ? pv[1].z : pv[1].w,
                    (j == 0) ? pv[2].x : (j == 1) ? pv[2].y : (j == 2) ? pv[2].z : pv[2].w,
                    (j == 0) ? pv[3].x : (j == 1) ? pv[3].y : (j == 2) ? pv[3].z : pv[3].w
                };
#pragma unroll
                for (int i = 0; i < 4; i++) {
                    unsigned long long pp = pack2(pj[i], pj[i]);
                    fma2(oacc[i][0], pp, vv.x);
                    fma2(oacc[i][1], pp, vv.y);
                }
            }
        }
#pragma unroll
        for (int i = 0; i < 4; i++) {
            size_t base = ((size_t)bh * (NH_ * T_) + c * 64 + q0 + i) * DH_ + f0;
#pragma unroll
            for (int j = 0; j < 2; j++) {
                float lo, hi;
                unpack2(oacc[i][j], lo, hi);
                *(float2*)(so + base + 2 * j) = make_float2(lo, hi);
            }
        }
    }
}

// ---------------- combine hash rounds ----------------
__global__ void __launch_bounds__(256) combine_kernel(const float* __restrict__ so,
                                                      const float* __restrict__ sl,
                                                      const int* __restrict__ sidx,
                                                      float* __restrict__ attn) {
    int t = blockIdx.x * 4 + (threadIdx.x >> 6);
    int bh = blockIdx.y;
    int f = threadIdx.x & 63;
    int b = bh >> 3, hd = bh & 7;
    int sbase = bh * (NH_ * T_);
    int sarr[NH_]; float lg[NH_];
    float m = -INFINITY;
#pragma unroll
    for (int h = 0; h < NH_; h++) {
        int s = sidx[sbase + h * T_ + t];
        sarr[h] = s;
        lg[h] = sl[sbase + s];
        m = fmaxf(m, lg[h]);
    }
    float den = 0.f;
#pragma unroll
    for (int h = 0; h < NH_; h++) den += expf(lg[h] - m);
    float out = 0.f;
#pragma unroll
    for (int h = 0; h < NH_; h++)
        out += (expf(lg[h] - m) / den) * so[((size_t)sbase + sarr[h]) * DH_ + f];
    attn[(b * T_ + t) * DIM_ + hd * DH_ + f] = out;
}

// ---------------- host orchestration ----------------
static float* sym_f(const void* s) { void* p = nullptr; cudaGetSymbolAddress(&p, s); return (float*)p; }
static int*   sym_i(const void* s) { void* p = nullptr; cudaGetSymbolAddress(&p, s); return (int*)p; }

extern "C" void kernel_launch(void* const* d_in, const int* in_sizes, int n_in,
                              void* d_out, int out_size) {
    const float* spec   = (const float*)d_in[0];
    const float* conv_w = (const float*)d_in[1];
    const float* conv_b = (const float*)d_in[2];
    const float* pe_row = (const float*)d_in[3];
    const float* pe_col = (const float*)d_in[4];
    const float* lnA_g  = (const float*)d_in[5];
    const float* lnA_b  = (const float*)d_in[6];
    const float* wqk    = (const float*)d_in[7];
    const float* wv     = (const float*)d_in[8];
    const float* wo     = (const float*)d_in[9];
    const float* bo     = (const float*)d_in[10];
    const float* lnF_g  = (const float*)d_in[11];
    const float* lnF_b  = (const float*)d_in[12];
    const float* w1     = (const float*)d_in[13];
    const float* b1     = (const float*)d_in[14];
    const float* w2     = (const float*)d_in[15];
    const float* b2     = (const float*)d_in[16];
    const float* lin_w  = (const float*)d_in[17];
    const float* lin_b  = (const float*)d_in[18];
    const float* rot    = (const float*)d_in[19];
    float* out = (float*)d_out;

    float* x1   = sym_f(g_x1);
    float* x2   = sym_f(g_x2);
    float* xn   = sym_f(g_xn);
    float* qkb  = sym_f(g_qk);
    float* vb   = sym_f(g_v);
    float* attn = sym_f(g_attn);
    float* ffn  = sym_f(g_ffn);
    float* yb   = sym_f(g_y);
    float* so   = sym_f(g_so);
    float* sl   = sym_f(g_sl);
    int* bucket = sym_i(g_bucket);
    int* st     = sym_i(g_st);
    int* sidx   = sym_i(g_sidx);

    cudaFuncSetAttribute(attn2_kernel, cudaFuncAttributeMaxDynamicSharedMemorySize, ATT_SMEM);
    cudaFuncSetAttribute(bucket_kernel, cudaFuncAttributeMaxDynamicSharedMemorySize, BKT_SMEM);

    // frontend
    conv_pe_kernel<<<dim3(T_, B_), 256>>>(spec, conv_w, conv_b, pe_row, pe_col, x1, x2);

    dim3 gQKV(DIM_ / 128, ROWS_ / 128, 2);
    dim3 g512(DIM_ / 128, ROWS_ / 128, 1);
    dim3 gffn(FFN_ / 128, ROWS_ / 128, 1);
    dim3 gout((NPITCH_ + 63) / 64, ROWS_ / 64);

    for (int l = 0; l < DEPTH_; l++) {
        const float* Wqk = wqk + (size_t)l * DIM_ * DIM_;
        const float* Wv  = wv  + (size_t)l * DIM_ * DIM_;
        const float* Wo  = wo  + (size_t)l * DIM_ * DIM_;
        const float* Bo  = bo  + (size_t)l * DIM_;
        const float* W1  = w1  + (size_t)l * DIM_ * FFN_;
        const float* B1  = b1  + (size_t)l * FFN_;
        const float* W2  = w2  + (size_t)l * DIM_ * FFN_;
        const float* B2  = b2  + (size_t)l * DIM_;
        const float* rotL = rot + (size_t)l * DH_ * NH_ * 16;

        // attention branch
        ln_kernel<<<ROWS_ / 8, 256>>>(x2, lnA_g + l * DIM_, lnA_b + l * DIM_, xn);
        sgemm128_kernel<<<gQKV, 256>>>(xn, Wqk, nullptr, qkb, Wv, vb, DIM_, DIM_, 0, 0);
        bucket_kernel<<<dim3(T_ / 64, BH_), 256, BKT_SMEM>>>(qkb, rotL, bucket);
        sort_kernel<<<dim3(NH_, BH_), 1024>>>(bucket, st, sidx);
        attn2_kernel<<<dim3(NCHUNK_, BH_), 256, ATT_SMEM>>>(qkb, vb, st, so, sl);
        combine_kernel<<<dim3(T_ / 4, BH_), 256>>>(so, sl, sidx, attn);
        sgemm128_kernel<<<g512, 256>>>(attn, Wo, Bo, x1, nullptr, nullptr, DIM_, DIM_, 0, 1);

        // ffn branch
        ln_kernel<<<ROWS_ / 8, 256>>>(x1, lnF_g + l * DIM_, lnF_b + l * DIM_, xn);
        sgemm128_kernel<<<gffn, 256>>>(xn, W1, B1, ffn, nullptr, nullptr, FFN_, DIM_, 2, 0);
        sgemm128_kernel<<<g512, 256>>>(ffn, W2, B2, x2, nullptr, nullptr, DIM_, FFN_, 0, 1);
    }

    // final projection with fused y = 0.5*(x1+x2)
    sgemm_kernel<<<gout, 256>>>(x1, lin_w, lin_b, out, x2, ROWS_, NPITCH_, DIM_, 0, 0);
    (void)yb;
}